// round 1
// baseline (speedup 1.0000x reference)
#include <cuda_runtime.h>
#include <math.h>

#define BATCH 8
#define SEQ   512
#define DMODEL 1024
#define NHEAD 16
#define DHEAD 64
#define MROWS (BATCH*SEQ)        // 4096

// scratch (no cudaMalloc allowed)
__device__ float g_qkv[(size_t)MROWS * 4 * DMODEL];  // 4096 x 4096  (64MB)
__device__ float g_att[(size_t)MROWS * DMODEL];      // 4096 x 1024  (16MB)

// ---------------------------------------------------------------------------
// SGEMM (NT):  C[m,n] = sum_k A[m,k]*B[n,k]  (+ bias[n])
// A: MxK row-major, B: NxK row-major, C: MxN row-major.
// 128x128 block tile, BK=32, 256 threads, 8x8 per thread.
// ---------------------------------------------------------------------------
#define BM 128
#define BN 128
#define BK 32

template<bool HAS_BIAS>
__global__ __launch_bounds__(256, 2)
void sgemm_nt(const float* __restrict__ A, const float* __restrict__ B,
              const float* __restrict__ bias, float* __restrict__ C,
              int M, int N, int K)
{
    __shared__ float As[BK][BM + 4];
    __shared__ float Bs[BK][BN + 4];

    const int tid  = threadIdx.x;
    const int bm   = blockIdx.y * BM;
    const int bn   = blockIdx.x * BN;
    const int arow = tid >> 3;          // 0..31
    const int acol = (tid & 7) * 4;     // 0,4,..,28
    const int tx   = tid & 15;
    const int ty   = tid >> 4;

    float acc[8][8];
#pragma unroll
    for (int i = 0; i < 8; i++)
#pragma unroll
        for (int j = 0; j < 8; j++) acc[i][j] = 0.f;

    for (int k0 = 0; k0 < K; k0 += BK) {
#pragma unroll
        for (int r = 0; r < 4; r++) {
            const int row = arow + 32 * r;
            float4 a = *(const float4*)(A + (size_t)(bm + row) * K + k0 + acol);
            As[acol + 0][row] = a.x; As[acol + 1][row] = a.y;
            As[acol + 2][row] = a.z; As[acol + 3][row] = a.w;
            float4 b = *(const float4*)(B + (size_t)(bn + row) * K + k0 + acol);
            Bs[acol + 0][row] = b.x; Bs[acol + 1][row] = b.y;
            Bs[acol + 2][row] = b.z; Bs[acol + 3][row] = b.w;
        }
        __syncthreads();
#pragma unroll
        for (int kk = 0; kk < BK; kk++) {
            float af[8], bf[8];
            *(float4*)&af[0] = *(const float4*)&As[kk][ty * 8];
            *(float4*)&af[4] = *(const float4*)&As[kk][ty * 8 + 4];
            *(float4*)&bf[0] = *(const float4*)&Bs[kk][tx * 8];
            *(float4*)&bf[4] = *(const float4*)&Bs[kk][tx * 8 + 4];
#pragma unroll
            for (int i = 0; i < 8; i++)
#pragma unroll
                for (int j = 0; j < 8; j++)
                    acc[i][j] += af[i] * bf[j];
        }
        __syncthreads();
    }

#pragma unroll
    for (int i = 0; i < 8; i++) {
        const int row = bm + ty * 8 + i;
        float* cp = C + (size_t)row * N + bn + tx * 8;
#pragma unroll
        for (int j = 0; j < 8; j += 4) {
            float4 v;
            v.x = acc[i][j + 0]; v.y = acc[i][j + 1];
            v.z = acc[i][j + 2]; v.w = acc[i][j + 3];
            if (HAS_BIAS) {
                v.x += bias[bn + tx * 8 + j + 0];
                v.y += bias[bn + tx * 8 + j + 1];
                v.z += bias[bn + tx * 8 + j + 2];
                v.w += bias[bn + tx * 8 + j + 3];
            }
            *(float4*)(cp + j) = v;
        }
    }
}

// ---------------------------------------------------------------------------
// Attention: one CTA per (b, h, 64-query tile).
// Scores for the full 512 keys materialized in smem, then softmax, then P@V.
// Dual keys (k1 self / k2 other speaker) selected by qmask equality.
// ---------------------------------------------------------------------------
#define LDV  68    // padded row stride (floats) for q/k/v tiles: conflict-free f4
#define LDSC 520   // padded row stride for score matrix

#define ATTN_SMEM_FLOATS (3 * 64 * LDV + 64 * LDSC)
#define ATTN_SMEM_BYTES  (ATTN_SMEM_FLOATS * 4 + 3 * 64 * 4)

__global__ __launch_bounds__(256, 1)
void attn_kernel(const int* __restrict__ mask, const int* __restrict__ qmask,
                 const float* __restrict__ shiftp, const float* __restrict__ biasp)
{
    extern __shared__ float sm[];
    float* sQ  = sm;                      // 64 * LDV
    float* sK1 = sQ  + 64 * LDV;
    float* sK2 = sK1 + 64 * LDV;          // reused as V buffer? no, sK1 reused
    float* sS  = sK2 + 64 * LDV;          // 64 * LDSC
    int*   sQm = (int*)(sS + 64 * LDSC);  // 64
    int*   sKm = sQm + 64;                // key qmask
    int*   sMk = sKm + 64;                // key padding mask

    const int tid  = threadIdx.x;
    const int tx   = tid & 15;
    const int ty   = tid >> 4;
    const int lane = tid & 31;
    const int wid  = tid >> 5;
    const int qt = blockIdx.x;   // 0..7
    const int h  = blockIdx.y;   // 0..15
    const int b  = blockIdx.z;   // 0..7

    const float shiftv   = shiftp[0];
    const float biasv    = biasp[0];
    const float invscale = 0.125f;        // 1/sqrt(64)

    const size_t rowbase = (size_t)b * SEQ;
    const int    cq = h * DHEAD;          // q column base inside qkv row

    // ---- load Q tile [64 x 64] ----
#pragma unroll
    for (int r = 0; r < 4; r++) {
        const int row = ty + 16 * r;
        float4 v = *(const float4*)(g_qkv + (rowbase + qt * 64 + row) * 4096 + cq + tx * 4);
        *(float4*)(sQ + row * LDV + tx * 4) = v;
    }
    if (tid < 64) sQm[tid] = qmask[b * SEQ + qt * 64 + tid];
    __syncthreads();

    // ---- score phase ----
    for (int kt = 0; kt < 8; kt++) {
#pragma unroll
        for (int r = 0; r < 4; r++) {
            const int row = ty + 16 * r;
            const size_t base = (rowbase + kt * 64 + row) * 4096 + cq + tx * 4;
            *(float4*)(sK1 + row * LDV + tx * 4) = *(const float4*)(g_qkv + base + 1024);
            *(float4*)(sK2 + row * LDV + tx * 4) = *(const float4*)(g_qkv + base + 2048);
        }
        if (tid < 64) {
            sKm[tid] = qmask[b * SEQ + kt * 64 + tid];
            sMk[tid] = mask [b * SEQ + kt * 64 + tid];
        }
        __syncthreads();

        float a1[4][4], a2[4][4];
#pragma unroll
        for (int i = 0; i < 4; i++)
#pragma unroll
            for (int j = 0; j < 4; j++) { a1[i][j] = 0.f; a2[i][j] = 0.f; }

#pragma unroll
        for (int d0 = 0; d0 < DHEAD; d0 += 4) {
            float4 qv[4], k1v[4], k2v[4];
#pragma unroll
            for (int i = 0; i < 4; i++)
                qv[i] = *(const float4*)(sQ + (ty + 16 * i) * LDV + d0);
#pragma unroll
            for (int j = 0; j < 4; j++) {
                k1v[j] = *(const float4*)(sK1 + (tx + 16 * j) * LDV + d0);
                k2v[j] = *(const float4*)(sK2 + (tx + 16 * j) * LDV + d0);
            }
#pragma unroll
            for (int i = 0; i < 4; i++)
#pragma unroll
                for (int j = 0; j < 4; j++) {
                    a1[i][j] += qv[i].x * k1v[j].x + qv[i].y * k1v[j].y
                              + qv[i].z * k1v[j].z + qv[i].w * k1v[j].w;
                    a2[i][j] += qv[i].x * k2v[j].x + qv[i].y * k2v[j].y
                              + qv[i].z * k2v[j].z + qv[i].w * k2v[j].w;
                }
        }

#pragma unroll
        for (int i = 0; i < 4; i++) {
            const int ql = ty + 16 * i;
            const float qg = (float)(qt * 64 + ql);
            const int qm = sQm[ql];
#pragma unroll
            for (int j = 0; j < 4; j++) {
                const int kl = tx + 16 * j;
                const int kg = kt * 64 + kl;
                float s = (qm == sKm[kl]) ? a1[i][j] : a2[i][j];
                s *= invscale;
                const float dd = qg - (float)kg;
                s -= (shiftv * dd * dd + biasv);
                if (sMk[kl] == 0) s = -1e30f;
                sS[ql * LDSC + kg] = s;
            }
        }
        __syncthreads();
    }

    // ---- softmax: each warp owns 8 rows ----
#pragma unroll
    for (int rr = 0; rr < 8; rr++) {
        const int q = wid * 8 + rr;
        float* rowp = sS + q * LDSC;
        float vals[16];
        float m = -1e30f;
#pragma unroll
        for (int c = 0; c < 16; c++) {
            vals[c] = rowp[lane + 32 * c];
            m = fmaxf(m, vals[c]);
        }
#pragma unroll
        for (int o = 16; o > 0; o >>= 1) m = fmaxf(m, __shfl_xor_sync(0xffffffffu, m, o));
        float sum = 0.f;
#pragma unroll
        for (int c = 0; c < 16; c++) { float e = __expf(vals[c] - m); vals[c] = e; sum += e; }
#pragma unroll
        for (int o = 16; o > 0; o >>= 1) sum += __shfl_xor_sync(0xffffffffu, sum, o);
        const float inv = 1.0f / sum;
#pragma unroll
        for (int c = 0; c < 16; c++) rowp[lane + 32 * c] = vals[c] * inv;
    }
    __syncthreads();

    // ---- P @ V ----  (thread: 4 queries ty+16i, 4 head-dims tx*4..+3)
    float o[4][4];
#pragma unroll
    for (int i = 0; i < 4; i++)
#pragma unroll
        for (int j = 0; j < 4; j++) o[i][j] = 0.f;

    for (int kt = 0; kt < 8; kt++) {
#pragma unroll
        for (int r = 0; r < 4; r++) {
            const int row = ty + 16 * r;
            *(float4*)(sK1 + row * LDV + tx * 4) =
                *(const float4*)(g_qkv + (rowbase + kt * 64 + row) * 4096 + cq + 3072 + tx * 4);
        }
        __syncthreads();

#pragma unroll 4
        for (int kk = 0; kk < 64; kk += 4) {
            float4 p4[4];
#pragma unroll
            for (int i = 0; i < 4; i++)
                p4[i] = *(const float4*)(sS + (ty + 16 * i) * LDSC + kt * 64 + kk);
#pragma unroll
            for (int u = 0; u < 4; u++) {
                float4 vv = *(const float4*)(sK1 + (kk + u) * LDV + tx * 4);
#pragma unroll
                for (int i = 0; i < 4; i++) {
                    const float p = (u == 0) ? p4[i].x : (u == 1) ? p4[i].y
                                  : (u == 2) ? p4[i].z : p4[i].w;
                    o[i][0] += p * vv.x; o[i][1] += p * vv.y;
                    o[i][2] += p * vv.z; o[i][3] += p * vv.w;
                }
            }
        }
        __syncthreads();
    }

#pragma unroll
    for (int i = 0; i < 4; i++) {
        const int q = qt * 64 + ty + 16 * i;
        float4 v;
        v.x = o[i][0]; v.y = o[i][1]; v.z = o[i][2]; v.w = o[i][3];
        *(float4*)(g_att + (rowbase + q) * DMODEL + h * DHEAD + tx * 4) = v;
    }
}

// ---------------------------------------------------------------------------
extern "C" void kernel_launch(void* const* d_in, const int* in_sizes, int n_in,
                              void* d_out, int out_size)
{
    const float* x     = (const float*)d_in[0];
    const int*   mask  = (const int*)  d_in[1];
    const int*   qmask = (const int*)  d_in[2];
    const float* Wqkv  = (const float*)d_in[3];
    const float* fc_w  = (const float*)d_in[4];
    const float* fc_b  = (const float*)d_in[5];
    const float* shift = (const float*)d_in[6];
    const float* bias  = (const float*)d_in[7];
    float* out = (float*)d_out;

    float* qkvbuf = nullptr;
    float* attbuf = nullptr;
    cudaGetSymbolAddress((void**)&qkvbuf, g_qkv);
    cudaGetSymbolAddress((void**)&attbuf, g_att);

    cudaFuncSetAttribute(attn_kernel, cudaFuncAttributeMaxDynamicSharedMemorySize,
                         ATTN_SMEM_BYTES);

    // 1) qkv = x @ Wqkv^T : [4096,1024] x [4096,1024]^T -> [4096,4096]
    {
        dim3 grid(4 * DMODEL / BN, MROWS / BM);   // (32, 32)
        sgemm_nt<false><<<grid, 256>>>(x, Wqkv, nullptr, qkvbuf,
                                       MROWS, 4 * DMODEL, DMODEL);
    }

    // 2) attention
    {
        dim3 grid(SEQ / 64, NHEAD, BATCH);        // (8, 16, 8)
        attn_kernel<<<grid, 256, ATTN_SMEM_BYTES>>>(mask, qmask, shift, bias);
    }

    // 3) out = att @ fc_w^T + fc_b : [4096,1024] x [1024,1024]^T -> [4096,1024]
    {
        dim3 grid(DMODEL / BN, MROWS / BM);       // (8, 32)
        sgemm_nt<true><<<grid, 256>>>(attbuf, fc_w, fc_b, out,
                                      MROWS, DMODEL, DMODEL);
    }
}

// round 3
// speedup vs baseline: 1.7953x; 1.7953x over previous
#include <cuda_runtime.h>
#include <cuda_bf16.h>
#include <math.h>
#include <stdint.h>

#define BATCH 8
#define SEQ   512
#define DMODEL 1024
#define NHEAD 16
#define DHEAD 64
#define MROWS (BATCH*SEQ)        // 4096

// ---------------- scratch (no cudaMalloc allowed) ----------------
__device__ float g_qkv[(size_t)MROWS * 4 * DMODEL];       // 4096 x 4096 fp32
__device__ float g_att[(size_t)MROWS * DMODEL];           // 4096 x 1024 fp32
__device__ __nv_bfloat16 g_Ah[(size_t)MROWS * DMODEL];
__device__ __nv_bfloat16 g_Al[(size_t)MROWS * DMODEL];
__device__ __nv_bfloat16 g_Bh[(size_t)MROWS * DMODEL];
__device__ __nv_bfloat16 g_Bl[(size_t)MROWS * DMODEL];

// ---------------------------------------------------------------------------
// fp32 -> bf16 hi/lo splitter (vectorized x4)
// ---------------------------------------------------------------------------
__global__ void split_bf16_v4(const float4* __restrict__ src,
                              uint2* __restrict__ hi, uint2* __restrict__ lo, int n4)
{
    int i = blockIdx.x * blockDim.x + threadIdx.x;
    if (i >= n4) return;
    float4 v = src[i];
    __nv_bfloat16 h0 = __float2bfloat16(v.x);
    __nv_bfloat16 h1 = __float2bfloat16(v.y);
    __nv_bfloat16 h2 = __float2bfloat16(v.z);
    __nv_bfloat16 h3 = __float2bfloat16(v.w);
    __nv_bfloat16 l0 = __float2bfloat16(v.x - __bfloat162float(h0));
    __nv_bfloat16 l1 = __float2bfloat16(v.y - __bfloat162float(h1));
    __nv_bfloat16 l2 = __float2bfloat16(v.z - __bfloat162float(h2));
    __nv_bfloat16 l3 = __float2bfloat16(v.w - __bfloat162float(h3));
    uint2 H, L;
    H.x = (uint32_t)__bfloat16_as_ushort(h0) | ((uint32_t)__bfloat16_as_ushort(h1) << 16);
    H.y = (uint32_t)__bfloat16_as_ushort(h2) | ((uint32_t)__bfloat16_as_ushort(h3) << 16);
    L.x = (uint32_t)__bfloat16_as_ushort(l0) | ((uint32_t)__bfloat16_as_ushort(l1) << 16);
    L.y = (uint32_t)__bfloat16_as_ushort(l2) | ((uint32_t)__bfloat16_as_ushort(l3) << 16);
    hi[i] = H;
    lo[i] = L;
}

// ---------------------------------------------------------------------------
// HMMA bf16-split GEMM (NT): C[m,n] = sum_k A[m,k]*B[n,k] (+bias[n])
// mma.sync.m16n8k16 row.col, ldmatrix from SW128-swizzled smem,
// cp.async double-buffered K-chunks of 64.
// ---------------------------------------------------------------------------
#define LDSM4(R0,R1,R2,R3,addr) \
    asm volatile("ldmatrix.sync.aligned.m8n8.x4.shared.b16 {%0,%1,%2,%3}, [%4];" \
        : "=r"(R0),"=r"(R1),"=r"(R2),"=r"(R3) : "r"(addr))

__device__ __forceinline__ void mma16816(float* c, const uint32_t* a,
                                         uint32_t b0, uint32_t b1)
{
    asm volatile(
        "mma.sync.aligned.m16n8k16.row.col.f32.bf16.bf16.f32 "
        "{%0,%1,%2,%3}, {%4,%5,%6,%7}, {%8,%9}, {%0,%1,%2,%3};"
        : "+f"(c[0]), "+f"(c[1]), "+f"(c[2]), "+f"(c[3])
        : "r"(a[0]), "r"(a[1]), "r"(a[2]), "r"(a[3]), "r"(b0), "r"(b1));
}

__device__ __forceinline__ uint32_t sw128(uint32_t off) {
    return off ^ ((off >> 3) & 0x70);
}

__global__ __launch_bounds__(256, 1)
void gemm_hmma_split(const __nv_bfloat16* __restrict__ Ah, const __nv_bfloat16* __restrict__ Al,
                     const __nv_bfloat16* __restrict__ Bh, const __nv_bfloat16* __restrict__ Bl,
                     const float* __restrict__ bias, float* __restrict__ C,
                     int N, int K)
{
    extern __shared__ __align__(1024) char smem[];   // 2 x 64KB stages
    const int tid  = threadIdx.x;
    const int wid  = tid >> 5;
    const int lane = tid & 31;
    const int bm   = blockIdx.y * 128;
    const int bn   = blockIdx.x * 128;
    const int wm   = (wid & 3) * 32;     // warp m-offset within tile
    const int wn   = (wid >> 2) * 64;    // warp n-offset within tile

    const uint32_t smem_u = (uint32_t)__cvta_generic_to_shared(smem);

    float acc[2][8][4];
#pragma unroll
    for (int i = 0; i < 2; i++)
#pragma unroll
        for (int j = 0; j < 8; j++)
#pragma unroll
            for (int q = 0; q < 4; q++) acc[i][j][q] = 0.f;

    // ---- async chunk loader: 4 tiles (Ah,Al,Bh,Bl) each 128 rows x 128B SW128
    auto load_chunk = [&](int buf, int kc) {
        const int k0 = kc * 64;
        const uint32_t base = smem_u + buf * 65536;
#pragma unroll
        for (int t = 0; t < 4; t++) {
            const __nv_bfloat16* src = (t == 0) ? Ah : (t == 1) ? Al : (t == 2) ? Bh : Bl;
            const int rb = (t < 2) ? bm : bn;
#pragma unroll
            for (int j = 0; j < 4; j++) {
                const int slot = j * 256 + tid;
                const int row  = slot >> 3;
                const int sl   = slot & 7;
                uint32_t off = sw128((uint32_t)(row * 128 + sl * 16));
                const __nv_bfloat16* g = src + (size_t)(rb + row) * K + k0 + sl * 8;
                uint32_t d = base + t * 16384 + off;
                asm volatile("cp.async.cg.shared.global [%0], [%1], 16;"
                             :: "r"(d), "l"(g));
            }
        }
        asm volatile("cp.async.commit_group;");
    };

    const int NC = K / 64;     // 16
    load_chunk(0, 0);
    load_chunk(1, 1);

    const int lrow = lane & 15;
    const int lhi  = lane >> 4;

    for (int c = 0; c < NC; c++) {
        asm volatile("cp.async.wait_group 1;");
        __syncthreads();
        const uint32_t b = smem_u + (c & 1) * 65536;

#pragma unroll
        for (int ks = 0; ks < 4; ks++) {
            uint32_t ah[2][4], al[2][4], bh[4][4], bl[4][4];
#pragma unroll
            for (int mi = 0; mi < 2; mi++) {
                const int row = wm + mi * 16 + lrow;
                uint32_t off = sw128((uint32_t)(row * 128 + (ks * 2 + lhi) * 16));
                LDSM4(ah[mi][0], ah[mi][1], ah[mi][2], ah[mi][3], b + off);
                LDSM4(al[mi][0], al[mi][1], al[mi][2], al[mi][3], b + 16384 + off);
            }
#pragma unroll
            for (int np = 0; np < 4; np++) {
                const int row = wn + np * 16 + lrow;
                uint32_t off = sw128((uint32_t)(row * 128 + (ks * 2 + lhi) * 16));
                LDSM4(bh[np][0], bh[np][1], bh[np][2], bh[np][3], b + 32768 + off);
                LDSM4(bl[np][0], bl[np][1], bl[np][2], bl[np][3], b + 49152 + off);
            }
#pragma unroll
            for (int mi = 0; mi < 2; mi++)
#pragma unroll
                for (int np = 0; np < 4; np++)
#pragma unroll
                    for (int hf = 0; hf < 2; hf++) {
                        const int nj = np * 2 + hf;
                        mma16816(acc[mi][nj], ah[mi], bh[np][hf], bh[np][2 + hf]);
                        mma16816(acc[mi][nj], ah[mi], bl[np][hf], bl[np][2 + hf]);
                        mma16816(acc[mi][nj], al[mi], bh[np][hf], bh[np][2 + hf]);
                    }
        }
        __syncthreads();
        if (c + 2 < NC) load_chunk(c & 1, c + 2);
    }

    // ---- epilogue: fp32 registers -> C
#pragma unroll
    for (int mi = 0; mi < 2; mi++) {
        const int m0 = bm + wm + mi * 16 + (lane >> 2);
#pragma unroll
        for (int nj = 0; nj < 8; nj++) {
            const int n0 = bn + wn + nj * 8 + (lane & 3) * 2;
            float2 v0, v1;
            v0.x = acc[mi][nj][0]; v0.y = acc[mi][nj][1];
            v1.x = acc[mi][nj][2]; v1.y = acc[mi][nj][3];
            if (bias) {
                const float b0 = bias[n0], b1 = bias[n0 + 1];
                v0.x += b0; v0.y += b1;
                v1.x += b0; v1.y += b1;
            }
            *(float2*)(C + (size_t)m0 * N + n0)       = v0;
            *(float2*)(C + (size_t)(m0 + 8) * N + n0) = v1;
        }
    }
}

// ---------------------------------------------------------------------------
// Attention: one CTA per (b, h, 64-query tile). (unchanged from R1)
// ---------------------------------------------------------------------------
#define LDV  68
#define LDSC 520
#define ATTN_SMEM_FLOATS (3 * 64 * LDV + 64 * LDSC)
#define ATTN_SMEM_BYTES  (ATTN_SMEM_FLOATS * 4 + 3 * 64 * 4)

__global__ __launch_bounds__(256, 1)
void attn_kernel(const int* __restrict__ mask, const int* __restrict__ qmask,
                 const float* __restrict__ shiftp, const float* __restrict__ biasp)
{
    extern __shared__ float sm[];
    float* sQ  = sm;
    float* sK1 = sQ  + 64 * LDV;
    float* sK2 = sK1 + 64 * LDV;
    float* sS  = sK2 + 64 * LDV;
    int*   sQm = (int*)(sS + 64 * LDSC);
    int*   sKm = sQm + 64;
    int*   sMk = sKm + 64;

    const int tid  = threadIdx.x;
    const int tx   = tid & 15;
    const int ty   = tid >> 4;
    const int lane = tid & 31;
    const int wid  = tid >> 5;
    const int qt = blockIdx.x;
    const int h  = blockIdx.y;
    const int b  = blockIdx.z;

    const float shiftv   = shiftp[0];
    const float biasv    = biasp[0];
    const float invscale = 0.125f;

    const size_t rowbase = (size_t)b * SEQ;
    const int    cq = h * DHEAD;

#pragma unroll
    for (int r = 0; r < 4; r++) {
        const int row = ty + 16 * r;
        float4 v = *(const float4*)(g_qkv + (rowbase + qt * 64 + row) * 4096 + cq + tx * 4);
        *(float4*)(sQ + row * LDV + tx * 4) = v;
    }
    if (tid < 64) sQm[tid] = qmask[b * SEQ + qt * 64 + tid];
    __syncthreads();

    for (int kt = 0; kt < 8; kt++) {
#pragma unroll
        for (int r = 0; r < 4; r++) {
            const int row = ty + 16 * r;
            const size_t base = (rowbase + kt * 64 + row) * 4096 + cq + tx * 4;
            *(float4*)(sK1 + row * LDV + tx * 4) = *(const float4*)(g_qkv + base + 1024);
            *(float4*)(sK2 + row * LDV + tx * 4) = *(const float4*)(g_qkv + base + 2048);
        }
        if (tid < 64) {
            sKm[tid] = qmask[b * SEQ + kt * 64 + tid];
            sMk[tid] = mask [b * SEQ + kt * 64 + tid];
        }
        __syncthreads();

        float a1[4][4], a2[4][4];
#pragma unroll
        for (int i = 0; i < 4; i++)
#pragma unroll
            for (int j = 0; j < 4; j++) { a1[i][j] = 0.f; a2[i][j] = 0.f; }

#pragma unroll
        for (int d0 = 0; d0 < DHEAD; d0 += 4) {
            float4 qv[4], k1v[4], k2v[4];
#pragma unroll
            for (int i = 0; i < 4; i++)
                qv[i] = *(const float4*)(sQ + (ty + 16 * i) * LDV + d0);
#pragma unroll
            for (int j = 0; j < 4; j++) {
                k1v[j] = *(const float4*)(sK1 + (tx + 16 * j) * LDV + d0);
                k2v[j] = *(const float4*)(sK2 + (tx + 16 * j) * LDV + d0);
            }
#pragma unroll
            for (int i = 0; i < 4; i++)
#pragma unroll
                for (int j = 0; j < 4; j++) {
                    a1[i][j] += qv[i].x * k1v[j].x + qv[i].y * k1v[j].y
                              + qv[i].z * k1v[j].z + qv[i].w * k1v[j].w;
                    a2[i][j] += qv[i].x * k2v[j].x + qv[i].y * k2v[j].y
                              + qv[i].z * k2v[j].z + qv[i].w * k2v[j].w;
                }
        }

#pragma unroll
        for (int i = 0; i < 4; i++) {
            const int ql = ty + 16 * i;
            const float qg = (float)(qt * 64 + ql);
            const int qm = sQm[ql];
#pragma unroll
            for (int j = 0; j < 4; j++) {
                const int kl = tx + 16 * j;
                const int kg = kt * 64 + kl;
                float s = (qm == sKm[kl]) ? a1[i][j] : a2[i][j];
                s *= invscale;
                const float dd = qg - (float)kg;
                s -= (shiftv * dd * dd + biasv);
                if (sMk[kl] == 0) s = -1e30f;
                sS[ql * LDSC + kg] = s;
            }
        }
        __syncthreads();
    }

#pragma unroll
    for (int rr = 0; rr < 8; rr++) {
        const int q = wid * 8 + rr;
        float* rowp = sS + q * LDSC;
        float vals[16];
        float m = -1e30f;
#pragma unroll
        for (int c = 0; c < 16; c++) {
            vals[c] = rowp[lane + 32 * c];
            m = fmaxf(m, vals[c]);
        }
#pragma unroll
        for (int o = 16; o > 0; o >>= 1) m = fmaxf(m, __shfl_xor_sync(0xffffffffu, m, o));
        float sum = 0.f;
#pragma unroll
        for (int c = 0; c < 16; c++) { float e = __expf(vals[c] - m); vals[c] = e; sum += e; }
#pragma unroll
        for (int o = 16; o > 0; o >>= 1) sum += __shfl_xor_sync(0xffffffffu, sum, o);
        const float inv = 1.0f / sum;
#pragma unroll
        for (int c = 0; c < 16; c++) rowp[lane + 32 * c] = vals[c] * inv;
    }
    __syncthreads();

    float o[4][4];
#pragma unroll
    for (int i = 0; i < 4; i++)
#pragma unroll
        for (int j = 0; j < 4; j++) o[i][j] = 0.f;

    for (int kt = 0; kt < 8; kt++) {
#pragma unroll
        for (int r = 0; r < 4; r++) {
            const int row = ty + 16 * r;
            *(float4*)(sK1 + row * LDV + tx * 4) =
                *(const float4*)(g_qkv + (rowbase + kt * 64 + row) * 4096 + cq + 3072 + tx * 4);
        }
        __syncthreads();

#pragma unroll 4
        for (int kk = 0; kk < 64; kk += 4) {
            float4 p4[4];
#pragma unroll
            for (int i = 0; i < 4; i++)
                p4[i] = *(const float4*)(sS + (ty + 16 * i) * LDSC + kt * 64 + kk);
#pragma unroll
            for (int u = 0; u < 4; u++) {
                float4 vv = *(const float4*)(sK1 + (kk + u) * LDV + tx * 4);
#pragma unroll
                for (int i = 0; i < 4; i++) {
                    const float p = (u == 0) ? p4[i].x : (u == 1) ? p4[i].y
                                  : (u == 2) ? p4[i].z : p4[i].w;
                    o[i][0] += p * vv.x; o[i][1] += p * vv.y;
                    o[i][2] += p * vv.z; o[i][3] += p * vv.w;
                }
            }
        }
        __syncthreads();
    }

#pragma unroll
    for (int i = 0; i < 4; i++) {
        const int q = qt * 64 + ty + 16 * i;
        float4 v;
        v.x = o[i][0]; v.y = o[i][1]; v.z = o[i][2]; v.w = o[i][3];
        *(float4*)(g_att + (rowbase + q) * DMODEL + h * DHEAD + tx * 4) = v;
    }
}

// ---------------------------------------------------------------------------
extern "C" void kernel_launch(void* const* d_in, const int* in_sizes, int n_in,
                              void* d_out, int out_size)
{
    const float* x     = (const float*)d_in[0];
    const int*   mask  = (const int*)  d_in[1];
    const int*   qmask = (const int*)  d_in[2];
    const float* Wqkv  = (const float*)d_in[3];
    const float* fc_w  = (const float*)d_in[4];
    const float* fc_b  = (const float*)d_in[5];
    const float* shift = (const float*)d_in[6];
    const float* bias  = (const float*)d_in[7];
    float* out = (float*)d_out;

    float* qkvbuf = nullptr;
    float* attbuf = nullptr;
    __nv_bfloat16 *ah, *al, *bh, *bl;
    cudaGetSymbolAddress((void**)&qkvbuf, g_qkv);
    cudaGetSymbolAddress((void**)&attbuf, g_att);
    cudaGetSymbolAddress((void**)&ah, g_Ah);
    cudaGetSymbolAddress((void**)&al, g_Al);
    cudaGetSymbolAddress((void**)&bh, g_Bh);
    cudaGetSymbolAddress((void**)&bl, g_Bl);

    cudaFuncSetAttribute(attn_kernel, cudaFuncAttributeMaxDynamicSharedMemorySize,
                         ATTN_SMEM_BYTES);
    cudaFuncSetAttribute(gemm_hmma_split, cudaFuncAttributeMaxDynamicSharedMemorySize,
                         131072);

    const int nA = MROWS * DMODEL;          // 4M elems

    // 1) split x and Wqkv into bf16 hi/lo
    split_bf16_v4<<<(nA / 4 + 255) / 256, 256>>>((const float4*)x,
                                                 (uint2*)ah, (uint2*)al, nA / 4);
    split_bf16_v4<<<(nA / 4 + 255) / 256, 256>>>((const float4*)Wqkv,
                                                 (uint2*)bh, (uint2*)bl, nA / 4);

    // 2) qkv = x @ Wqkv^T  -> [4096, 4096] fp32
    {
        dim3 grid(4 * DMODEL / 128, MROWS / 128);   // (32, 32)
        gemm_hmma_split<<<grid, 256, 131072>>>(ah, al, bh, bl, nullptr, qkvbuf,
                                               4 * DMODEL, DMODEL);
    }

    // 3) attention (fp32)
    {
        dim3 grid(SEQ / 64, NHEAD, BATCH);
        attn_kernel<<<grid, 256, ATTN_SMEM_BYTES>>>(mask, qmask, shift, bias);
    }

    // 4) split att and fc_w
    split_bf16_v4<<<(nA / 4 + 255) / 256, 256>>>((const float4*)attbuf,
                                                 (uint2*)ah, (uint2*)al, nA / 4);
    const int nW = DMODEL * DMODEL;          // 1M elems
    split_bf16_v4<<<(nW / 4 + 255) / 256, 256>>>((const float4*)fc_w,
                                                 (uint2*)bh, (uint2*)bl, nW / 4);

    // 5) out = att @ fc_w^T + fc_b -> [4096, 1024] fp32
    {
        dim3 grid(DMODEL / 128, MROWS / 128);       // (8, 32)
        gemm_hmma_split<<<grid, 256, 131072>>>(ah, al, bh, bl, fc_b, out,
                                               DMODEL, DMODEL);
    }
}

// round 4
// speedup vs baseline: 2.7271x; 1.5190x over previous
#include <cuda_runtime.h>
#include <cuda_bf16.h>
#include <math.h>
#include <stdint.h>

#define BATCH 8
#define SEQ   512
#define DMODEL 1024
#define NHEAD 16
#define DHEAD 64
#define MROWS (BATCH*SEQ)        // 4096

// ---------------- scratch (no cudaMalloc allowed) ----------------
__device__ __nv_bfloat16 g_Qh[(size_t)MROWS * 4 * DMODEL];  // qkv hi (32MB)
__device__ __nv_bfloat16 g_Ql[(size_t)MROWS * 4 * DMODEL];  // qkv lo (32MB)
__device__ __nv_bfloat16 g_Ah[(size_t)MROWS * DMODEL];      // A-split hi
__device__ __nv_bfloat16 g_Al[(size_t)MROWS * DMODEL];      // A-split lo
__device__ __nv_bfloat16 g_Bh[(size_t)MROWS * DMODEL];      // B-split hi
__device__ __nv_bfloat16 g_Bl[(size_t)MROWS * DMODEL];      // B-split lo

// ---------------------------------------------------------------------------
__device__ __forceinline__ uint32_t pkbf2(float a, float b) {
    __nv_bfloat162 t = __floats2bfloat162_rn(a, b);
    return *reinterpret_cast<uint32_t*>(&t);
}

__global__ void split_bf16_v4(const float4* __restrict__ src,
                              uint2* __restrict__ hi, uint2* __restrict__ lo, int n4)
{
    int i = blockIdx.x * blockDim.x + threadIdx.x;
    if (i >= n4) return;
    float4 v = src[i];
    float h0 = __bfloat162float(__float2bfloat16(v.x));
    float h1 = __bfloat162float(__float2bfloat16(v.y));
    float h2 = __bfloat162float(__float2bfloat16(v.z));
    float h3 = __bfloat162float(__float2bfloat16(v.w));
    uint2 H, L;
    H.x = pkbf2(v.x, v.y);          H.y = pkbf2(v.z, v.w);
    L.x = pkbf2(v.x - h0, v.y - h1); L.y = pkbf2(v.z - h2, v.w - h3);
    hi[i] = H;
    lo[i] = L;
}

// ---------------------------------------------------------------------------
#define LDSM4(R0,R1,R2,R3,addr) \
    asm volatile("ldmatrix.sync.aligned.m8n8.x4.shared.b16 {%0,%1,%2,%3}, [%4];" \
        : "=r"(R0),"=r"(R1),"=r"(R2),"=r"(R3) : "r"(addr))
#define LDSM4T(R0,R1,R2,R3,addr) \
    asm volatile("ldmatrix.sync.aligned.m8n8.x4.trans.shared.b16 {%0,%1,%2,%3}, [%4];" \
        : "=r"(R0),"=r"(R1),"=r"(R2),"=r"(R3) : "r"(addr))
#define CPASYNC16(dst, src) \
    asm volatile("cp.async.cg.shared.global [%0], [%1], 16;" :: "r"(dst), "l"(src))
#define CPCOMMIT() asm volatile("cp.async.commit_group;")
#define CPWAIT(n)  asm volatile("cp.async.wait_group %0;" :: "n"(n))

__device__ __forceinline__ void mma16816(float* c, const uint32_t* a,
                                         uint32_t b0, uint32_t b1)
{
    asm volatile(
        "mma.sync.aligned.m16n8k16.row.col.f32.bf16.bf16.f32 "
        "{%0,%1,%2,%3}, {%4,%5,%6,%7}, {%8,%9}, {%0,%1,%2,%3};"
        : "+f"(c[0]), "+f"(c[1]), "+f"(c[2]), "+f"(c[3])
        : "r"(a[0]), "r"(a[1]), "r"(a[2]), "r"(a[3]), "r"(b0), "r"(b1));
}

__device__ __forceinline__ uint32_t sw128(uint32_t off) {
    return off ^ ((off >> 3) & 0x70);
}

// ---------------------------------------------------------------------------
// HMMA bf16-split GEMM (NT), templated epilogue:
// SPLIT=false: fp32 C (+bias).  SPLIT=true: write bf16 hi/lo split outputs.
// ---------------------------------------------------------------------------
template<bool SPLIT>
__global__ __launch_bounds__(256, 1)
void gemm_hmma(const __nv_bfloat16* __restrict__ Ah, const __nv_bfloat16* __restrict__ Al,
               const __nv_bfloat16* __restrict__ Bh, const __nv_bfloat16* __restrict__ Bl,
               const float* __restrict__ bias, float* __restrict__ C,
               __nv_bfloat16* __restrict__ Ch, __nv_bfloat16* __restrict__ Cl,
               int N, int K)
{
    extern __shared__ __align__(1024) char smem[];   // 2 x 64KB stages
    const int tid  = threadIdx.x;
    const int wid  = tid >> 5;
    const int lane = tid & 31;
    const int bm   = blockIdx.y * 128;
    const int bn   = blockIdx.x * 128;
    const int wm   = (wid & 3) * 32;
    const int wn   = (wid >> 2) * 64;

    const uint32_t smem_u = (uint32_t)__cvta_generic_to_shared(smem);

    float acc[2][8][4];
#pragma unroll
    for (int i = 0; i < 2; i++)
#pragma unroll
        for (int j = 0; j < 8; j++)
#pragma unroll
            for (int q = 0; q < 4; q++) acc[i][j][q] = 0.f;

    auto load_chunk = [&](int buf, int kc) {
        const int k0 = kc * 64;
        const uint32_t base = smem_u + buf * 65536;
#pragma unroll
        for (int t = 0; t < 4; t++) {
            const __nv_bfloat16* src = (t == 0) ? Ah : (t == 1) ? Al : (t == 2) ? Bh : Bl;
            const int rb = (t < 2) ? bm : bn;
#pragma unroll
            for (int j = 0; j < 4; j++) {
                const int slot = j * 256 + tid;
                const int row  = slot >> 3;
                const int sl   = slot & 7;
                uint32_t off = sw128((uint32_t)(row * 128 + sl * 16));
                const __nv_bfloat16* g = src + (size_t)(rb + row) * K + k0 + sl * 8;
                CPASYNC16(base + t * 16384 + off, g);
            }
        }
        CPCOMMIT();
    };

    const int NC = K / 64;
    load_chunk(0, 0);
    load_chunk(1, 1);

    const int lrow = lane & 15;
    const int lhi  = lane >> 4;

    for (int c = 0; c < NC; c++) {
        CPWAIT(1);
        __syncthreads();
        const uint32_t b = smem_u + (c & 1) * 65536;

#pragma unroll
        for (int ks = 0; ks < 4; ks++) {
            uint32_t ah[2][4], al[2][4], bh[4][4], bl[4][4];
#pragma unroll
            for (int mi = 0; mi < 2; mi++) {
                const int row = wm + mi * 16 + lrow;
                uint32_t off = sw128((uint32_t)(row * 128 + (ks * 2 + lhi) * 16));
                LDSM4(ah[mi][0], ah[mi][1], ah[mi][2], ah[mi][3], b + off);
                LDSM4(al[mi][0], al[mi][1], al[mi][2], al[mi][3], b + 16384 + off);
            }
#pragma unroll
            for (int np = 0; np < 4; np++) {
                const int row = wn + np * 16 + lrow;
                uint32_t off = sw128((uint32_t)(row * 128 + (ks * 2 + lhi) * 16));
                LDSM4(bh[np][0], bh[np][1], bh[np][2], bh[np][3], b + 32768 + off);
                LDSM4(bl[np][0], bl[np][1], bl[np][2], bl[np][3], b + 49152 + off);
            }
#pragma unroll
            for (int mi = 0; mi < 2; mi++)
#pragma unroll
                for (int np = 0; np < 4; np++)
#pragma unroll
                    for (int hf = 0; hf < 2; hf++) {
                        const int nj = np * 2 + hf;
                        mma16816(acc[mi][nj], ah[mi], bh[np][hf], bh[np][2 + hf]);
                        mma16816(acc[mi][nj], ah[mi], bl[np][hf], bl[np][2 + hf]);
                        mma16816(acc[mi][nj], al[mi], bh[np][hf], bh[np][2 + hf]);
                    }
        }
        __syncthreads();
        if (c + 2 < NC) load_chunk(c & 1, c + 2);
    }

#pragma unroll
    for (int mi = 0; mi < 2; mi++) {
        const int m0 = bm + wm + mi * 16 + (lane >> 2);
#pragma unroll
        for (int nj = 0; nj < 8; nj++) {
            const int n0 = bn + wn + nj * 8 + (lane & 3) * 2;
#pragma unroll
            for (int hh = 0; hh < 2; hh++) {
                const int m = m0 + hh * 8;
                float v0 = acc[mi][nj][hh * 2 + 0];
                float v1 = acc[mi][nj][hh * 2 + 1];
                if (SPLIT) {
                    float h0 = __bfloat162float(__float2bfloat16(v0));
                    float h1 = __bfloat162float(__float2bfloat16(v1));
                    *(uint32_t*)(Ch + (size_t)m * N + n0) = pkbf2(v0, v1);
                    *(uint32_t*)(Cl + (size_t)m * N + n0) = pkbf2(v0 - h0, v1 - h1);
                } else {
                    float2 v;
                    v.x = v0 + bias[n0];
                    v.y = v1 + bias[n0 + 1];
                    *(float2*)(C + (size_t)m * N + n0) = v;
                }
            }
        }
    }
}

// ---------------------------------------------------------------------------
// HMMA attention.  CTA = (b, h, 64-query tile) over all 512 keys.
// 8 warps: 2 (m=32q) x 4 (n=16 keys / 16 dh).
// ---------------------------------------------------------------------------
#define LDSC 516
#define OFF_SS 0
#define OFF_QH 132096
#define OFF_QL 140288
#define OFF_KV 148480
#define OFF_P  214016
#define OFF_QM 230400
#define OFF_KM 230464
#define OFF_MK 230976
#define ATTN_SMEM 231488

__global__ __launch_bounds__(256, 1)
void attn_hmma(const int* __restrict__ mask, const int* __restrict__ qmask,
               const float* __restrict__ shiftp, const float* __restrict__ biasp)
{
    extern __shared__ __align__(1024) char sm8[];
    float* sS   = (float*)(sm8 + OFF_SS);
    char*  sQm8 = sm8 + OFF_QM;
    char*  sKm8 = sm8 + OFF_KM;
    char*  sMk8 = sm8 + OFF_MK;

    const int tid  = threadIdx.x;
    const int lane = tid & 31;
    const int wid  = tid >> 5;
    const int qt = blockIdx.x, h = blockIdx.y, b = blockIdx.z;

    const int mbase = (wid & 1) * 32;       // warp query base (0/32)
    const int nb16  = (wid >> 1) * 16;      // warp key/dh base (0..48)
    const int lrow  = lane & 15;
    const int lhi   = lane >> 4;

    const uint32_t su  = (uint32_t)__cvta_generic_to_shared(sm8);
    const uint32_t uQ  = su + OFF_QH;
    const uint32_t uKV = su + OFF_KV;
    const uint32_t uP  = su + OFF_P;

    const float shiftv = shiftp[0];
    const float biasv  = biasp[0];
    const size_t rowb  = (size_t)b * SEQ;

    // stage masks
    if (tid < 64) sQm8[tid] = (char)qmask[rowb + qt * 64 + tid];
    for (int i = tid; i < 512; i += 256) {
        sKm8[i] = (char)qmask[rowb + i];
        sMk8[i] = (char)mask [rowb + i];
    }

    // ---- Q tile loads (hi, lo) : group 0
#pragma unroll
    for (int t = 0; t < 2; t++) {
        const __nv_bfloat16* src = t ? g_Ql : g_Qh;
#pragma unroll
        for (int j = 0; j < 2; j++) {
            const int slot = j * 256 + tid;
            const int row = slot >> 3, sl = slot & 7;
            uint32_t d = uQ + t * 8192 + sw128((uint32_t)(row * 128 + sl * 16));
            CPASYNC16(d, src + (rowb + qt * 64 + row) * 4096 + h * 64 + sl * 8);
        }
    }
    CPCOMMIT();

    // ---- K chunk loader (k1h,k1l,k2h,k2l) -> 32KB buf
    auto ldK = [&](int buf, int kt) {
        const uint32_t base = uKV + buf * 32768;
#pragma unroll
        for (int t = 0; t < 4; t++) {
            const __nv_bfloat16* src = (t & 1) ? g_Ql : g_Qh;
            const int colb = ((t >> 1) ? 2048 : 1024) + h * 64;
#pragma unroll
            for (int j = 0; j < 2; j++) {
                const int slot = j * 256 + tid;
                const int row = slot >> 3, sl = slot & 7;
                uint32_t d = base + t * 8192 + sw128((uint32_t)(row * 128 + sl * 16));
                CPASYNC16(d, src + (rowb + kt * 64 + row) * 4096 + colb + sl * 8);
            }
        }
        CPCOMMIT();
    };
    // ---- V chunk loader (vh, vl) -> 16KB of buf
    auto ldV = [&](int buf, int kt) {
        const uint32_t base = uKV + buf * 32768;
#pragma unroll
        for (int t = 0; t < 2; t++) {
            const __nv_bfloat16* src = t ? g_Ql : g_Qh;
#pragma unroll
            for (int j = 0; j < 2; j++) {
                const int slot = j * 256 + tid;
                const int row = slot >> 3, sl = slot & 7;
                uint32_t d = base + t * 8192 + sw128((uint32_t)(row * 128 + sl * 16));
                CPASYNC16(d, src + (rowb + kt * 64 + row) * 4096 + 3072 + h * 64 + sl * 8);
            }
        }
        CPCOMMIT();
    };

    ldK(0, 0);
    ldK(1, 1);

    // wait for Q (leave K0,K1 pending), preload Q fragments
    CPWAIT(2);
    __syncthreads();

    uint32_t qh[4][2][4], ql[4][2][4];
#pragma unroll
    for (int ks = 0; ks < 4; ks++)
#pragma unroll
        for (int mi = 0; mi < 2; mi++) {
            uint32_t off = sw128((uint32_t)((mbase + mi * 16 + lrow) * 128 + (ks * 2 + lhi) * 16));
            LDSM4(qh[ks][mi][0], qh[ks][mi][1], qh[ks][mi][2], qh[ks][mi][3], uQ + off);
            LDSM4(ql[ks][mi][0], ql[ks][mi][1], ql[ks][mi][2], ql[ks][mi][3], uQ + 8192 + off);
        }

    // per-thread fixed query rows
    int   qrow[2][2];
    char  qm[2][2];
    float qgf[2][2];
#pragma unroll
    for (int mi = 0; mi < 2; mi++)
#pragma unroll
        for (int hh = 0; hh < 2; hh++) {
            qrow[mi][hh] = mbase + mi * 16 + (lane >> 2) + hh * 8;
            qm[mi][hh]   = sQm8[qrow[mi][hh]];
            qgf[mi][hh]  = (float)(qt * 64 + qrow[mi][hh]);
        }

    // ================= score phase =================
    for (int kt = 0; kt < 8; kt++) {
        CPWAIT(1);
        __syncthreads();
        const uint32_t kb = uKV + (kt & 1) * 32768;

        float a1[2][2][4], a2[2][2][4];
#pragma unroll
        for (int mi = 0; mi < 2; mi++)
#pragma unroll
            for (int nf = 0; nf < 2; nf++)
#pragma unroll
                for (int q = 0; q < 4; q++) { a1[mi][nf][q] = 0.f; a2[mi][nf][q] = 0.f; }

#pragma unroll
        for (int ks = 0; ks < 4; ks++) {
            uint32_t k1h[4], k1l[4], k2h[4], k2l[4];
            uint32_t off = sw128((uint32_t)((nb16 + lrow) * 128 + (ks * 2 + lhi) * 16));
            LDSM4(k1h[0], k1h[1], k1h[2], k1h[3], kb + off);
            LDSM4(k1l[0], k1l[1], k1l[2], k1l[3], kb + 8192 + off);
            LDSM4(k2h[0], k2h[1], k2h[2], k2h[3], kb + 16384 + off);
            LDSM4(k2l[0], k2l[1], k2l[2], k2l[3], kb + 24576 + off);
#pragma unroll
            for (int mi = 0; mi < 2; mi++)
#pragma unroll
                for (int nf = 0; nf < 2; nf++) {
                    mma16816(a1[mi][nf], qh[ks][mi], k1h[nf], k1h[2 + nf]);
                    mma16816(a1[mi][nf], qh[ks][mi], k1l[nf], k1l[2 + nf]);
                    mma16816(a1[mi][nf], ql[ks][mi], k1h[nf], k1h[2 + nf]);
                    mma16816(a2[mi][nf], qh[ks][mi], k2h[nf], k2h[2 + nf]);
                    mma16816(a2[mi][nf], qh[ks][mi], k2l[nf], k2l[2 + nf]);
                    mma16816(a2[mi][nf], ql[ks][mi], k2h[nf], k2h[2 + nf]);
                }
        }

        // select/scale/bias/mask -> sS
#pragma unroll
        for (int nf = 0; nf < 2; nf++)
#pragma unroll
            for (int e = 0; e < 2; e++) {
                const int kl = nb16 + nf * 8 + (lane & 3) * 2 + e;
                const int kg = kt * 64 + kl;
                const char km = sKm8[kg];
                const char mk = sMk8[kg];
                const float kgfv = (float)kg;
#pragma unroll
                for (int mi = 0; mi < 2; mi++)
#pragma unroll
                    for (int hh = 0; hh < 2; hh++) {
                        const float v1 = a1[mi][nf][hh * 2 + e];
                        const float v2 = a2[mi][nf][hh * 2 + e];
                        float s = (qm[mi][hh] == km) ? v1 : v2;
                        const float dd = qgf[mi][hh] - kgfv;
                        s = s * 0.125f - (shiftv * dd * dd + biasv);
                        if (!mk) s = -1e30f;
                        sS[qrow[mi][hh] * LDSC + kg] = s;
                    }
            }
        __syncthreads();
        if (kt + 2 < 8) ldK(kt & 1, kt + 2);
    }

    // prefetch V0, V1
    ldV(0, 0);
    ldV(1, 1);

    // ================= softmax (warp per row) =================
#pragma unroll
    for (int rr = 0; rr < 8; rr++) {
        const int q = wid * 8 + rr;
        float* rowp = sS + q * LDSC;
        float vals[16];
        float m = -1e30f;
#pragma unroll
        for (int c = 0; c < 16; c++) {
            vals[c] = rowp[lane + 32 * c];
            m = fmaxf(m, vals[c]);
        }
#pragma unroll
        for (int o = 16; o > 0; o >>= 1) m = fmaxf(m, __shfl_xor_sync(0xffffffffu, m, o));
        float sum = 0.f;
#pragma unroll
        for (int c = 0; c < 16; c++) { float e = __expf(vals[c] - m); vals[c] = e; sum += e; }
#pragma unroll
        for (int o = 16; o > 0; o >>= 1) sum += __shfl_xor_sync(0xffffffffu, sum, o);
        const float inv = 1.0f / sum;
#pragma unroll
        for (int c = 0; c < 16; c++) rowp[lane + 32 * c] = vals[c] * inv;
    }
    __syncthreads();

    // ================= P @ V =================
    float o[2][2][4];
#pragma unroll
    for (int mi = 0; mi < 2; mi++)
#pragma unroll
        for (int nf = 0; nf < 2; nf++)
#pragma unroll
            for (int q = 0; q < 4; q++) o[mi][nf][q] = 0.f;

    const int prow = tid >> 2;
    const int ps0  = (tid & 3) * 2;

    for (int c = 0; c < 8; c++) {
        CPWAIT(1);
        // convert P chunk -> sP hi/lo (bf16, sw128 rows of 128B)
#pragma unroll
        for (int s = ps0; s <= ps0 + 1; s++) {
            const float* p = sS + prow * LDSC + c * 64 + s * 8;
            float4 u = ((const float4*)p)[0];
            float4 w = ((const float4*)p)[1];
            float vv[8] = {u.x, u.y, u.z, u.w, w.x, w.y, w.z, w.w};
            uint4 HH, LL;
            uint32_t* Hp = (uint32_t*)&HH;
            uint32_t* Lp = (uint32_t*)&LL;
#pragma unroll
            for (int q = 0; q < 4; q++) {
                float f0 = vv[2 * q], f1 = vv[2 * q + 1];
                float h0 = __bfloat162float(__float2bfloat16(f0));
                float h1 = __bfloat162float(__float2bfloat16(f1));
                Hp[q] = pkbf2(f0, f1);
                Lp[q] = pkbf2(f0 - h0, f1 - h1);
            }
            uint32_t off = sw128((uint32_t)(prow * 128 + s * 16));
            *(uint4*)(sm8 + OFF_P + off)        = HH;
            *(uint4*)(sm8 + OFF_P + 8192 + off) = LL;
        }
        __syncthreads();

        const uint32_t vb = uKV + (c & 1) * 32768;
#pragma unroll
        for (int ks = 0; ks < 4; ks++) {
            uint32_t aPh[2][4], aPl[2][4], vh[4], vl[4];
#pragma unroll
            for (int mi = 0; mi < 2; mi++) {
                uint32_t off = sw128((uint32_t)((mbase + mi * 16 + lrow) * 128 + (ks * 2 + lhi) * 16));
                LDSM4(aPh[mi][0], aPh[mi][1], aPh[mi][2], aPh[mi][3], uP + off);
                LDSM4(aPl[mi][0], aPl[mi][1], aPl[mi][2], aPl[mi][3], uP + 8192 + off);
            }
            {
                const int quad = lane >> 3, r = lane & 7;
                uint32_t boff = sw128((uint32_t)((ks * 16 + (quad & 1) * 8 + r) * 128
                                                 + nb16 * 2 + (quad >> 1) * 16));
                LDSM4T(vh[0], vh[1], vh[2], vh[3], vb + boff);
                LDSM4T(vl[0], vl[1], vl[2], vl[3], vb + 8192 + boff);
            }
#pragma unroll
            for (int mi = 0; mi < 2; mi++)
#pragma unroll
                for (int nf = 0; nf < 2; nf++) {
                    mma16816(o[mi][nf], aPh[mi], vh[nf * 2], vh[nf * 2 + 1]);
                    mma16816(o[mi][nf], aPh[mi], vl[nf * 2], vl[nf * 2 + 1]);
                    mma16816(o[mi][nf], aPl[mi], vh[nf * 2], vh[nf * 2 + 1]);
                }
        }
        __syncthreads();
        if (c + 2 < 8) ldV(c & 1, c + 2);
    }

    // ---- epilogue: write hi/lo bf16 att into g_Ah/g_Al
#pragma unroll
    for (int mi = 0; mi < 2; mi++)
#pragma unroll
        for (int hh = 0; hh < 2; hh++) {
            const size_t row = rowb + qt * 64 + mbase + mi * 16 + (lane >> 2) + hh * 8;
#pragma unroll
            for (int nf = 0; nf < 2; nf++) {
                const int col = h * 64 + nb16 + nf * 8 + (lane & 3) * 2;
                float v0 = o[mi][nf][hh * 2 + 0];
                float v1 = o[mi][nf][hh * 2 + 1];
                float h0 = __bfloat162float(__float2bfloat16(v0));
                float h1 = __bfloat162float(__float2bfloat16(v1));
                *(uint32_t*)(g_Ah + row * DMODEL + col) = pkbf2(v0, v1);
                *(uint32_t*)(g_Al + row * DMODEL + col) = pkbf2(v0 - h0, v1 - h1);
            }
        }
}

// ---------------------------------------------------------------------------
extern "C" void kernel_launch(void* const* d_in, const int* in_sizes, int n_in,
                              void* d_out, int out_size)
{
    const float* x     = (const float*)d_in[0];
    const int*   mask  = (const int*)  d_in[1];
    const int*   qmask = (const int*)  d_in[2];
    const float* Wqkv  = (const float*)d_in[3];
    const float* fc_w  = (const float*)d_in[4];
    const float* fc_b  = (const float*)d_in[5];
    const float* shift = (const float*)d_in[6];
    const float* bias  = (const float*)d_in[7];
    float* out = (float*)d_out;

    __nv_bfloat16 *qh, *ql, *ah, *al, *bh, *bl;
    cudaGetSymbolAddress((void**)&qh, g_Qh);
    cudaGetSymbolAddress((void**)&ql, g_Ql);
    cudaGetSymbolAddress((void**)&ah, g_Ah);
    cudaGetSymbolAddress((void**)&al, g_Al);
    cudaGetSymbolAddress((void**)&bh, g_Bh);
    cudaGetSymbolAddress((void**)&bl, g_Bl);

    cudaFuncSetAttribute(gemm_hmma<true>,  cudaFuncAttributeMaxDynamicSharedMemorySize, 131072);
    cudaFuncSetAttribute(gemm_hmma<false>, cudaFuncAttributeMaxDynamicSharedMemorySize, 131072);
    cudaFuncSetAttribute(attn_hmma, cudaFuncAttributeMaxDynamicSharedMemorySize, ATTN_SMEM);

    const int nA = MROWS * DMODEL;          // 4M
    const int nW = DMODEL * DMODEL;         // 1M

    // 1) split x, Wqkv
    split_bf16_v4<<<(nA / 4 + 255) / 256, 256>>>((const float4*)x,
                                                 (uint2*)ah, (uint2*)al, nA / 4);
    split_bf16_v4<<<(nA / 4 + 255) / 256, 256>>>((const float4*)Wqkv,
                                                 (uint2*)bh, (uint2*)bl, nA / 4);

    // 2) qkv = x @ Wqkv^T, epilogue writes hi/lo bf16 directly
    {
        dim3 grid(4 * DMODEL / 128, MROWS / 128);   // (32, 32)
        gemm_hmma<true><<<grid, 256, 131072>>>(ah, al, bh, bl, nullptr, nullptr,
                                               qh, ql, 4 * DMODEL, DMODEL);
    }

    // 3) split fc_w (reuses B buffers after GEMM1)
    split_bf16_v4<<<(nW / 4 + 255) / 256, 256>>>((const float4*)fc_w,
                                                 (uint2*)bh, (uint2*)bl, nW / 4);

    // 4) attention (HMMA), writes hi/lo att into g_Ah/g_Al
    {
        dim3 grid(SEQ / 64, NHEAD, BATCH);          // (8, 16, 8)
        attn_hmma<<<grid, 256, ATTN_SMEM>>>(mask, qmask, shift, bias);
    }

    // 5) out = att @ fc_w^T + fc_b (fp32 epilogue)
    {
        dim3 grid(DMODEL / 128, MROWS / 128);       // (8, 32)
        gemm_hmma<false><<<grid, 256, 131072>>>(ah, al, bh, bl, fc_b, out,
                                                nullptr, nullptr, DMODEL, DMODEL);
    }
}